// round 16
// baseline (speedup 1.0000x reference)
#include <cuda_runtime.h>
#include <cuda_bf16.h>
#include <math.h>
#include <stdint.h>

// ---------------------------------------------------------------------------
// MambaSSD — split-bf16 mma.sync GEMMs; 256x128 CTA tiles (512 thr), 2-stage
// cp.async pipeline; proj retiled to 64-row CTAs for full-chip utilization.
// out = ((C*h + D*xi) * silu(z)) @ W_out
// ---------------------------------------------------------------------------

#define BATCH 4
#define SEQ   2048
#define DM    1024
#define DI    2048
#define DS    64
#define MTOK  (BATCH * SEQ)   // 8192
#define NCH   16
#define CHUNK 128

// ------------------------- scratch (device globals) ------------------------
__device__ float g_xi[MTOK * DI];
__device__ float g_sz[MTOK * DI];
__device__ float g_a[MTOK];
__device__ float g_B[MTOK * DI];
__device__ float g_C[MTOK * DI];
__device__ float g_Hend[BATCH * NCH * DI];
__device__ float g_Hcarry[BATCH * NCH * DI];
__device__ float g_Aprod[BATCH * NCH];
__device__ __nv_bfloat16 g_xh[MTOK * DM];
__device__ __nv_bfloat16 g_xl[MTOK * DM];
__device__ __nv_bfloat16 g_xih[MTOK * DI];
__device__ __nv_bfloat16 g_xil[MTOK * DI];
__device__ __nv_bfloat16 g_yh[MTOK * DI];
__device__ __nv_bfloat16 g_yl[MTOK * DI];
__device__ __nv_bfloat16 g_Brh[MTOK * DS];
__device__ __nv_bfloat16 g_Brl[MTOK * DS];
__device__ __nv_bfloat16 g_Crh[MTOK * DS];
__device__ __nv_bfloat16 g_Crl[MTOK * DS];
__device__ __nv_bfloat16 g_Wih[(2 * DI) * DM];
__device__ __nv_bfloat16 g_Wil[(2 * DI) * DM];
__device__ __nv_bfloat16 g_Woh[DM * DI];
__device__ __nv_bfloat16 g_Wol[DM * DI];
__device__ __nv_bfloat16 g_WBh[DI * DS];
__device__ __nv_bfloat16 g_WBl[DI * DS];
__device__ __nv_bfloat16 g_WCh[DI * DS];
__device__ __nv_bfloat16 g_WCl[DI * DS];
#define PN 144
__device__ __nv_bfloat16 g_Wxh[PN * DI];
__device__ __nv_bfloat16 g_Wxl[PN * DI];

// ------------------------------ PTX helpers --------------------------------
__device__ __forceinline__ uint32_t smem_u32(const void* p) {
    uint32_t a;
    asm("{ .reg .u64 t; cvta.to.shared.u64 t, %1; cvt.u32.u64 %0, t; }"
        : "=r"(a) : "l"(p));
    return a;
}

__device__ __forceinline__ void mma16816(float* d, const uint32_t* a, const uint32_t* b) {
    asm volatile(
        "mma.sync.aligned.m16n8k16.row.col.f32.bf16.bf16.f32 "
        "{%0,%1,%2,%3}, {%4,%5,%6,%7}, {%8,%9}, {%0,%1,%2,%3};"
        : "+f"(d[0]), "+f"(d[1]), "+f"(d[2]), "+f"(d[3])
        : "r"(a[0]), "r"(a[1]), "r"(a[2]), "r"(a[3]), "r"(b[0]), "r"(b[1]));
}

__device__ __forceinline__ void ldsm4(uint32_t* r, uint32_t addr) {
    asm volatile("ldmatrix.sync.aligned.m8n8.x4.shared.b16 {%0,%1,%2,%3}, [%4];"
                 : "=r"(r[0]), "=r"(r[1]), "=r"(r[2]), "=r"(r[3]) : "r"(addr));
}
__device__ __forceinline__ void ldsm2(uint32_t* r, uint32_t addr) {
    asm volatile("ldmatrix.sync.aligned.m8n8.x2.shared.b16 {%0,%1}, [%2];"
                 : "=r"(r[0]), "=r"(r[1]) : "r"(addr));
}

__device__ __forceinline__ void cp16(uint32_t saddr, const void* g) {
    asm volatile("cp.async.cg.shared.global [%0], [%1], 16;"
                 :: "r"(saddr), "l"(g) : "memory");
}
#define CP_COMMIT()   asm volatile("cp.async.commit_group;" ::: "memory")
#define CP_WAIT(n)    asm volatile("cp.async.wait_group %0;" :: "n"(n) : "memory")

__device__ __forceinline__ uint32_t pack_bf2(float a, float b) {
    __nv_bfloat162 t = __floats2bfloat162_rn(a, b);
    return *(uint32_t*)&t;
}

#define KPAD 40                    // smem row stride in bf16 (80B), conflict-free
#define A_B  (256 * KPAD * 2)      // A array bytes per stage (20480)
#define B_B  (128 * KPAD * 2)      // B array bytes per stage (10240)
#define STG_B (2 * A_B + 2 * B_B)  // 61440
#define MMA_SMEM (2 * STG_B)       // 122880

// ------ mma.sync split-bf16 GEMM, 256x128 tile, 512 thr, 2-stage pipe ------
// 16 warps: warpM=wid>>1 (0..7), warpN=wid&1; warp tile 32x64.
template<int EPI>
__device__ void mma_gemm2_dev(const __nv_bfloat16* __restrict__ Ahi,
                              const __nv_bfloat16* __restrict__ Alo,
                              const __nv_bfloat16* __restrict__ Bhi,
                              const __nv_bfloat16* __restrict__ Blo,
                              float* __restrict__ Cout, int N, int K)
{
    extern __shared__ __align__(16) char smem[];
    const uint32_t sb = smem_u32(smem);

    const int tid  = threadIdx.x;
    const int wid  = tid >> 5;
    const int lane = tid & 31;
    const int warpM = wid >> 1;       // 0..7
    const int warpN = wid & 1;
    const int rowBase = blockIdx.y * 256;
    const int colBase = blockIdx.x * 128;
    const int NC = K / 32;

    float acc[2][8][4];
#pragma unroll
    for (int i = 0; i < 2; i++)
#pragma unroll
        for (int j = 0; j < 8; j++)
#pragma unroll
            for (int q = 0; q < 4; q++) acc[i][j][q] = 0.f;

    auto issue = [&](int c, int st) {
        const uint32_t s0 = sb + (uint32_t)st * STG_B;
#pragma unroll
        for (int s = tid; s < 1024; s += 512) {       // A: 256 rows x 4 q
            const int row = s >> 2, q = s & 3;
            const uint32_t so = s0 + (uint32_t)(row * KPAD + q * 8) * 2;
            const size_t ga = (size_t)(rowBase + row) * K + c * 32 + q * 8;
            cp16(so,       Ahi + ga);
            cp16(so + A_B, Alo + ga);
        }
        {                                              // B: 128 rows x 4 q
            const int s = tid & 511;
            const int row = s >> 2, q = s & 3;
            const uint32_t so = s0 + 2 * A_B + (uint32_t)(row * KPAD + q * 8) * 2;
            const size_t gb = (size_t)(colBase + row) * K + c * 32 + q * 8;
            cp16(so,       Bhi + gb);
            cp16(so + B_B, Blo + gb);
        }
        CP_COMMIT();
    };

    issue(0, 0);
    for (int c = 0; c < NC; ++c) {
        if (c + 1 < NC) { issue(c + 1, (c + 1) & 1); CP_WAIT(1); }
        else            { CP_WAIT(0); }
        __syncthreads();

        const uint32_t ahB = sb + (uint32_t)(c & 1) * STG_B;
        const uint32_t alB = ahB + A_B;
        const uint32_t bhB = ahB + 2 * A_B;
        const uint32_t blB = bhB + B_B;

#pragma unroll
        for (int ks = 0; ks < 2; ks++) {
            const int k0 = ks * 16;
            uint32_t ah[2][4], al[2][4];
#pragma unroll
            for (int mi = 0; mi < 2; mi++) {
                const int m0 = warpM * 32 + mi * 16;
                const uint32_t off =
                    (uint32_t)(((m0 + (lane & 15)) * KPAD + k0 + (lane >> 4) * 8) * 2);
                ldsm4(ah[mi], ahB + off);
                ldsm4(al[mi], alB + off);
            }
#pragma unroll
            for (int njp = 0; njp < 4; njp++) {
                const int n0 = warpN * 64 + njp * 16;
                const uint32_t off = (uint32_t)(((n0 + (lane & 7) + ((lane >> 4) & 1) * 8)
                                     * KPAD + k0 + ((lane >> 3) & 1) * 8) * 2);
                uint32_t bh[4], bl[4];
                ldsm4(bh, bhB + off);
                ldsm4(bl, blB + off);
#pragma unroll
                for (int mi = 0; mi < 2; mi++) {
                    mma16816(acc[mi][njp * 2],     ah[mi], bh);
                    mma16816(acc[mi][njp * 2],     ah[mi], bl);
                    mma16816(acc[mi][njp * 2],     al[mi], bh);
                    mma16816(acc[mi][njp * 2 + 1], ah[mi], bh + 2);
                    mma16816(acc[mi][njp * 2 + 1], ah[mi], bl + 2);
                    mma16816(acc[mi][njp * 2 + 1], al[mi], bh + 2);
                }
            }
        }
        __syncthreads();
    }

    const int qr = lane >> 2, qc = lane & 3;
#pragma unroll
    for (int mi = 0; mi < 2; mi++) {
#pragma unroll
        for (int nj = 0; nj < 8; nj++) {
            const int m0 = rowBase + warpM * 32 + mi * 16;
            const int nn = warpN * 64 + nj * 8 + qc * 2;
            float c0 = acc[mi][nj][0], c1 = acc[mi][nj][1];
            float c2 = acc[mi][nj][2], c3 = acc[mi][nj][3];
            if (EPI == 0) {
                *(float2*)(Cout + (size_t)(m0 + qr) * N + colBase + nn)     = make_float2(c0, c1);
                *(float2*)(Cout + (size_t)(m0 + qr + 8) * N + colBase + nn) = make_float2(c2, c3);
            } else {
                const bool zside = (colBase >= DI);
                const int cb = (zside ? colBase - DI : colBase) + nn;
                if (zside) {
                    c0 = c0 / (1.f + expf(-c0));
                    c1 = c1 / (1.f + expf(-c1));
                    c2 = c2 / (1.f + expf(-c2));
                    c3 = c3 / (1.f + expf(-c3));
                    *(float2*)(g_sz + (size_t)(m0 + qr) * DI + cb)     = make_float2(c0, c1);
                    *(float2*)(g_sz + (size_t)(m0 + qr + 8) * DI + cb) = make_float2(c2, c3);
                } else {
                    *(float2*)(g_xi + (size_t)(m0 + qr) * DI + cb)     = make_float2(c0, c1);
                    *(float2*)(g_xi + (size_t)(m0 + qr + 8) * DI + cb) = make_float2(c2, c3);
                    __nv_bfloat16 h0 = __float2bfloat16(c0), h1 = __float2bfloat16(c1);
                    __nv_bfloat16 h2 = __float2bfloat16(c2), h3 = __float2bfloat16(c3);
                    *(uint32_t*)(g_xih + (size_t)(m0 + qr) * DI + cb) =
                        pack_bf2(__bfloat162float(h0), __bfloat162float(h1));
                    *(uint32_t*)(g_xih + (size_t)(m0 + qr + 8) * DI + cb) =
                        pack_bf2(__bfloat162float(h2), __bfloat162float(h3));
                    *(uint32_t*)(g_xil + (size_t)(m0 + qr) * DI + cb) =
                        pack_bf2(c0 - __bfloat162float(h0), c1 - __bfloat162float(h1));
                    *(uint32_t*)(g_xil + (size_t)(m0 + qr + 8) * DI + cb) =
                        pack_bf2(c2 - __bfloat162float(h2), c3 - __bfloat162float(h3));
                }
            }
        }
    }
}

__global__ __launch_bounds__(512, 1)
void k_mma_in()
{
    mma_gemm2_dev<1>(g_xh, g_xl, g_Wih, g_Wil, nullptr, 2 * DI, DM);
}

__global__ __launch_bounds__(512, 1)
void k_mma_out(float* __restrict__ out)
{
    mma_gemm2_dev<0>(g_yh, g_yl, g_Woh, g_Wol, out, DM, DI);
}

__global__ __launch_bounds__(512, 1)
void k_mma_bc()
{
    if (blockIdx.z == 0)
        mma_gemm2_dev<0>(g_Brh, g_Brl, g_WBh, g_WBl, g_B, DI, DS);
    else
        mma_gemm2_dev<0>(g_Crh, g_Crl, g_WCh, g_WCl, g_C, DI, DS);
}

// -------------------- activation split: x -> g_xh/g_xl ---------------------
__global__ __launch_bounds__(256)
void k_split_x(const float* __restrict__ x)
{
    const int idx4 = blockIdx.x * 256 + threadIdx.x;
    const size_t base = (size_t)idx4 * 4;
    float4 v = *(const float4*)(x + base);
    float f[4] = {v.x, v.y, v.z, v.w};
    float lf[4];
    __nv_bfloat16 h[4];
#pragma unroll
    for (int j = 0; j < 4; j++) {
        h[j] = __float2bfloat16(f[j]);
        lf[j] = f[j] - __bfloat162float(h[j]);
    }
    *(uint2*)(g_xh + base) = make_uint2(
        pack_bf2(__bfloat162float(h[0]), __bfloat162float(h[1])),
        pack_bf2(__bfloat162float(h[2]), __bfloat162float(h[3])));
    *(uint2*)(g_xl + base) = make_uint2(pack_bf2(lf[0], lf[1]), pack_bf2(lf[2], lf[3]));
}

// -------- proj = xi @ W_xp (N pad 144), 64-row CTA tiles, grid 128 ---------
__device__ __forceinline__ void proj_store(int m, int col, float v, float Aval)
{
    if (col == 0) {
        float dlt = (v > 20.f) ? v : log1pf(expf(v));
        g_a[m] = expf(Aval * dlt);
    } else if (col <= 2 * DS) {
        __nv_bfloat16 h = __float2bfloat16(v);
        __nv_bfloat16 l = __float2bfloat16(v - __bfloat162float(h));
        if (col <= DS) {
            g_Brh[(size_t)m * DS + (col - 1)] = h;
            g_Brl[(size_t)m * DS + (col - 1)] = l;
        } else {
            g_Crh[(size_t)m * DS + (col - 1 - DS)] = h;
            g_Crl[(size_t)m * DS + (col - 1 - DS)] = l;
        }
    }
}

__global__ __launch_bounds__(256, 2)
void k_proj_mma(const float* __restrict__ A_log)
{
    __shared__ __align__(16) __nv_bfloat16 sAh[64 * KPAD];
    __shared__ __align__(16) __nv_bfloat16 sAl[64 * KPAD];
    __shared__ __align__(16) __nv_bfloat16 sBh[PN * KPAD];
    __shared__ __align__(16) __nv_bfloat16 sBl[PN * KPAD];

    const int tid  = threadIdx.x;
    const int wid  = tid >> 5;
    const int lane = tid & 31;
    const int warpM = wid >> 1;       // 0..3, one m16 tile each
    const int warpN = wid & 1;        // 0..1, 72 cols each
    const int rowBase = blockIdx.x * 64;
    const int NC = DI / 32;

    const uint32_t ahB = smem_u32(sAh);
    const uint32_t alB = smem_u32(sAl);
    const uint32_t bhB = smem_u32(sBh);
    const uint32_t blB = smem_u32(sBl);

    float acc[9][4];
#pragma unroll
    for (int j = 0; j < 9; j++)
#pragma unroll
        for (int q = 0; q < 4; q++) acc[j][q] = 0.f;

    for (int c = 0; c < NC; ++c) {
        __syncthreads();
        if (tid < 256) {                      // A: 64 rows x 4 q = 256 slots
            const int row = tid >> 2, q = tid & 3;
            const uint32_t so = (uint32_t)(row * KPAD + q * 8) * 2;
            const size_t ga = (size_t)(rowBase + row) * DI + c * 32 + q * 8;
            cp16(ahB + so, g_xih + ga);
            cp16(alB + so, g_xil + ga);
        }
        for (int i = tid; i < PN * 4; i += 256) {
            const int row = i >> 2, q = i & 3;
            const size_t go = (size_t)row * DI + c * 32 + q * 8;
            const uint32_t so = (uint32_t)(row * KPAD + q * 8) * 2;
            cp16(bhB + so, g_Wxh + go);
            cp16(blB + so, g_Wxl + go);
        }
        CP_COMMIT();
        CP_WAIT(0);
        __syncthreads();

#pragma unroll
        for (int ks = 0; ks < 2; ks++) {
            const int k0 = ks * 16;
            uint32_t ah[4], al[4];
            {
                const int m0 = warpM * 16;
                const uint32_t off =
                    (uint32_t)(((m0 + (lane & 15)) * KPAD + k0 + (lane >> 4) * 8) * 2);
                ldsm4(ah, ahB + off);
                ldsm4(al, alB + off);
            }
#pragma unroll
            for (int nj = 0; nj < 9; nj++) {
                const int n0 = warpN * 72 + nj * 8;
                const uint32_t off =
                    (uint32_t)(((n0 + (lane & 7)) * KPAD + k0 + ((lane >> 3) & 1) * 8) * 2);
                uint32_t bh[2], bl[2];
                ldsm2(bh, bhB + off);
                ldsm2(bl, blB + off);
                mma16816(acc[nj], ah, bh);
                mma16816(acc[nj], ah, bl);
                mma16816(acc[nj], al, bh);
            }
        }
    }

    const float Aval = -expf(*A_log);
    const int qr = lane >> 2, qc = lane & 3;
#pragma unroll
    for (int nj = 0; nj < 9; nj++) {
        const int m0 = rowBase + warpM * 16;
        const int nn = warpN * 72 + nj * 8 + qc * 2;
        proj_store(m0 + qr,     nn,     acc[nj][0], Aval);
        proj_store(m0 + qr,     nn + 1, acc[nj][1], Aval);
        proj_store(m0 + qr + 8, nn,     acc[nj][2], Aval);
        proj_store(m0 + qr + 8, nn + 1, acc[nj][3], Aval);
    }
}

// -------------------- weight transpose + bf16 hi/lo split -------------------
__device__ void wsplit_dev(const float* __restrict__ W,
                           __nv_bfloat16* __restrict__ Thi,
                           __nv_bfloat16* __restrict__ Tlo, int K, int N)
{
    __shared__ float ts[32][33];
    const int n0 = blockIdx.x * 32, k0 = blockIdx.y * 32;
    const int tx = threadIdx.x, ty = threadIdx.y;
    for (int i = ty; i < 32; i += 8)
        ts[i][tx] = W[(size_t)(k0 + i) * N + n0 + tx];
    __syncthreads();
    for (int i = ty; i < 32; i += 8) {
        float v = ts[tx][i];
        __nv_bfloat16 h = __float2bfloat16(v);
        float lf = v - __bfloat162float(h);
        size_t o = (size_t)(n0 + i) * K + k0 + tx;
        Thi[o] = h;
        Tlo[o] = __float2bfloat16(lf);
    }
}

__global__ __launch_bounds__(256)
void k_wsplit_in(const float* __restrict__ W) { wsplit_dev(W, g_Wih, g_Wil, DM, 2 * DI); }
__global__ __launch_bounds__(256)
void k_wsplit_out(const float* __restrict__ W) { wsplit_dev(W, g_Woh, g_Wol, DI, DM); }

__global__ __launch_bounds__(256)
void k_wsplit_xp(const float* __restrict__ Wxp)
{
    const int idx = blockIdx.x * 256 + threadIdx.x;
    if (idx >= PN * DI) return;
    const int n = idx / DI, k = idx % DI;
    float v = (n < 129) ? Wxp[(size_t)k * 129 + n] : 0.f;
    __nv_bfloat16 h = __float2bfloat16(v);
    g_Wxh[idx] = h;
    g_Wxl[idx] = __float2bfloat16(v - __bfloat162float(h));
}

__global__ __launch_bounds__(256)
void k_wsplit_bc(const float* __restrict__ W_B, const float* __restrict__ W_C)
{
    const int idx = blockIdx.x * 256 + threadIdx.x;
    if (idx >= DI * DS) return;
    const int n = idx / DS, k = idx % DS;
    {
        float v = W_B[(size_t)k * DI + n];
        __nv_bfloat16 h = __float2bfloat16(v);
        g_WBh[idx] = h;
        g_WBl[idx] = __float2bfloat16(v - __bfloat162float(h));
    }
    {
        float v = W_C[(size_t)k * DI + n];
        __nv_bfloat16 h = __float2bfloat16(v);
        g_WCh[idx] = h;
        g_WCl[idx] = __float2bfloat16(v - __bfloat162float(h));
    }
}

// ------------------------------- 3-phase scan ------------------------------
__global__ __launch_bounds__(256)
void scan_chunk_kernel()
{
    __shared__ float as_[CHUNK];
    const int d = blockIdx.x * blockDim.x + threadIdx.x;
    const int c = blockIdx.y, b = blockIdx.z;
    const int m0 = b * SEQ + c * CHUNK;
    if (threadIdx.x < CHUNK) as_[threadIdx.x] = g_a[m0 + threadIdx.x];
    __syncthreads();

    const float* bp = g_B  + (size_t)m0 * DI + d;
    const float* xp = g_xi + (size_t)m0 * DI + d;
    float h = 0.f;
#pragma unroll 4
    for (int t = 0; t < CHUNK; t++)
        h = fmaf(as_[t], h, bp[(size_t)t * DI] * xp[(size_t)t * DI]);

    g_Hend[((size_t)(b * NCH + c)) * DI + d] = h;
    if (blockIdx.x == 0 && threadIdx.x == 0) {
        float ap = 1.f;
#pragma unroll
        for (int t = 0; t < CHUNK; t++) ap *= as_[t];
        g_Aprod[b * NCH + c] = ap;
    }
}

__global__ __launch_bounds__(256)
void scan_carry_kernel()
{
    const int idx = blockIdx.x * blockDim.x + threadIdx.x;
    const int b = idx / DI, d = idx % DI;
    float carry = 0.f;
#pragma unroll
    for (int c = 0; c < NCH; c++) {
        size_t o = ((size_t)(b * NCH + c)) * DI + d;
        g_Hcarry[o] = carry;
        carry = fmaf(g_Aprod[b * NCH + c], carry, g_Hend[o]);
    }
}

__global__ __launch_bounds__(256)
void scan_final_kernel(const float* __restrict__ Dvec)
{
    __shared__ float as_[CHUNK];
    const int d = blockIdx.x * blockDim.x + threadIdx.x;
    const int c = blockIdx.y, b = blockIdx.z;
    const int m0 = b * SEQ + c * CHUNK;
    if (threadIdx.x < CHUNK) as_[threadIdx.x] = g_a[m0 + threadIdx.x];
    __syncthreads();

    const float* bp  = g_B  + (size_t)m0 * DI + d;
    const float* xp  = g_xi + (size_t)m0 * DI + d;
    const float* cp  = g_C  + (size_t)m0 * DI + d;
    const float* szp = g_sz + (size_t)m0 * DI + d;
    __nv_bfloat16* yhp = g_yh + (size_t)m0 * DI + d;
    __nv_bfloat16* ylp = g_yl + (size_t)m0 * DI + d;

    const float Dd = Dvec[d];
    float h = g_Hcarry[((size_t)(b * NCH + c)) * DI + d];
#pragma unroll 4
    for (int t = 0; t < CHUNK; t++) {
        float xv = xp[(size_t)t * DI];
        h = fmaf(as_[t], h, bp[(size_t)t * DI] * xv);
        float yv = fmaf(cp[(size_t)t * DI], h, Dd * xv);
        yv *= szp[(size_t)t * DI];
        __nv_bfloat16 yh = __float2bfloat16(yv);
        float yl = yv - __bfloat162float(yh);
        yhp[(size_t)t * DI] = yh;
        ylp[(size_t)t * DI] = __float2bfloat16(yl);
    }
}

// --------------------------------- launch ----------------------------------
extern "C" void kernel_launch(void* const* d_in, const int* in_sizes, int n_in,
                              void* d_out, int out_size)
{
    const float* x     = (const float*)d_in[0];
    const float* W_in  = (const float*)d_in[1];
    const float* W_xp  = (const float*)d_in[2];
    const float* W_B   = (const float*)d_in[3];
    const float* W_C   = (const float*)d_in[4];
    const float* W_out = (const float*)d_in[5];
    const float* Dvec  = (const float*)d_in[6];
    const float* A_log = (const float*)d_in[7];
    float* out = (float*)d_out;

    cudaFuncSetAttribute(k_mma_in,  cudaFuncAttributeMaxDynamicSharedMemorySize, MMA_SMEM);
    cudaFuncSetAttribute(k_mma_out, cudaFuncAttributeMaxDynamicSharedMemorySize, MMA_SMEM);
    cudaFuncSetAttribute(k_mma_bc,  cudaFuncAttributeMaxDynamicSharedMemorySize, MMA_SMEM);

    // 0) weight + activation splits
    k_wsplit_in <<<dim3((2 * DI) / 32, DM / 32), dim3(32, 8)>>>(W_in);
    k_wsplit_out<<<dim3(DM / 32, DI / 32),      dim3(32, 8)>>>(W_out);
    k_wsplit_xp <<<(PN * DI + 255) / 256, 256>>>(W_xp);
    k_wsplit_bc <<<(DI * DS + 255) / 256, 256>>>(W_B, W_C);
    k_split_x   <<<(MTOK * DM / 4) / 256, 256>>>(x);
    // 1) xz = x @ W_in -> xi (fp32 + bf16 split), silu(z)
    k_mma_in<<<dim3((2 * DI) / 128, MTOK / 256), 512, MMA_SMEM>>>();
    // 2) proj = xi @ W_xp -> a, Braw(hi/lo), Craw(hi/lo)
    k_proj_mma<<<MTOK / 64, 256>>>(A_log);
    // 3) B = Braw @ W_B ; C = Craw @ W_C
    k_mma_bc<<<dim3(DI / 128, MTOK / 256, 2), 512, MMA_SMEM>>>();
    // 4) chunked scan + gating -> y (split bf16)
    scan_chunk_kernel<<<dim3(DI / 256, NCH, BATCH), 256>>>();
    scan_carry_kernel<<<(BATCH * DI) / 256, 256>>>();
    scan_final_kernel<<<dim3(DI / 256, NCH, BATCH), 256>>>(Dvec);
    // 5) out = y @ W_out
    k_mma_out<<<dim3(DM / 128, MTOK / 256), 512, MMA_SMEM>>>(out);
}